// round 4
// baseline (speedup 1.0000x reference)
#include <cuda_runtime.h>
#include <cstdint>
#include <math.h>

#define B_ROWS 131072
#define DIM    512
#define CTX    128
#define HID    2048
#define KIN    384
#define S_MAX  5.0f

// ---------------------------------------------------------------------------
// Scratch device globals (no allocations allowed)
// ---------------------------------------------------------------------------
__device__ float g_A1 [(size_t)B_ROWS * KIN];   // gathered [x_even | ctx], tf32-rounded
__device__ float g_h  [(size_t)B_ROWS * HID];   // relu(A1 @ W1 + b1), tf32-rounded
__device__ float g_st [(size_t)B_ROWS * DIM];   // h @ W2 + b2
__device__ float g_W1r[(size_t)KIN * HID];      // W1 tf32-rounded
__device__ float g_W2r[(size_t)HID * DIM];      // W2 tf32-rounded

// ---------------------------------------------------------------------------
// helpers
// ---------------------------------------------------------------------------
__device__ __forceinline__ uint32_t smem_to_u32(const void* p) {
    uint32_t a;
    asm("{ .reg .u64 t; cvta.to.shared.u64 t, %1; cvt.u32.u64 %0, t; }" : "=r"(a) : "l"(p));
    return a;
}
__device__ __forceinline__ float to_tf32(float v) {
    uint32_t r;
    asm("cvt.rna.tf32.f32 %0, %1;" : "=r"(r) : "f"(v));
    return __uint_as_float(r);
}
__device__ __forceinline__ void cp_async16(uint32_t saddr, const void* gptr) {
    asm volatile("cp.async.ca.shared.global [%0], [%1], 16;" :: "r"(saddr), "l"(gptr));
}
#define CP_COMMIT() asm volatile("cp.async.commit_group;" ::: "memory")
#define CP_WAIT(n)  asm volatile("cp.async.wait_group %0;" :: "n"(n) : "memory")

__device__ __forceinline__ void mma_tf32(float* d, const uint32_t* a, const uint32_t* b) {
    asm volatile(
        "mma.sync.aligned.m16n8k8.row.col.f32.tf32.tf32.f32 "
        "{%0,%1,%2,%3}, {%4,%5,%6,%7}, {%8,%9}, {%0,%1,%2,%3};\n"
        : "+f"(d[0]), "+f"(d[1]), "+f"(d[2]), "+f"(d[3])
        : "r"(a[0]), "r"(a[1]), "r"(a[2]), "r"(a[3]), "r"(b[0]), "r"(b[1]));
}

// ---------------------------------------------------------------------------
// Prep kernels
// ---------------------------------------------------------------------------
__global__ __launch_bounds__(256)
void gather_kernel(const float* __restrict__ x, const float* __restrict__ ctx)
{
    int idx = blockIdx.x * 256 + threadIdx.x;          // over B_ROWS*96 float4s
    int b  = idx / 96;
    int k4 = idx % 96;
    float4 v;
    if (k4 < 64) {
        const float* xp = &x[(size_t)b * DIM + 8 * k4];
        v.x = xp[0]; v.y = xp[2]; v.z = xp[4]; v.w = xp[6];
    } else {
        v = *(const float4*)&ctx[(size_t)b * CTX + (k4 - 64) * 4];
    }
    v.x = to_tf32(v.x); v.y = to_tf32(v.y); v.z = to_tf32(v.z); v.w = to_tf32(v.w);
    *(float4*)&g_A1[(size_t)b * KIN + k4 * 4] = v;
}

__global__ __launch_bounds__(256)
void round_kernel(const float* __restrict__ src, float* __restrict__ dst)
{
    int idx = blockIdx.x * 256 + threadIdx.x;   // over n/4 float4s
    float4 v = *(const float4*)&src[idx * 4];
    v.x = to_tf32(v.x); v.y = to_tf32(v.y); v.z = to_tf32(v.z); v.w = to_tf32(v.w);
    *(float4*)&dst[idx * 4] = v;
}

// ---------------------------------------------------------------------------
// GEMM via mma.sync tf32. Block 128x128, 4 warps (64x64 each), BK=32,
// 3-stage cp.async pipeline, 1 sync/stage. All operands tf32-pre-rounded.
// ---------------------------------------------------------------------------
#define LDA 36     // floats; bank(4*gid + tig) bijective over lanes
#define LDB 136    // floats; bank(8*tig + gid) bijective over lanes
#define ABYTES (128 * LDA * 4)          // 18432
#define BBYTES (32 * LDB * 4)           // 17408
#define BUFBYTES (ABYTES + BBYTES)      // 35840
#define NSTAGE 3
#define GEMM_SMEM (NSTAGE * BUFBYTES)   // 107520

template<int K_TOTAL, bool RELU_ROUND>
__global__ __launch_bounds__(128, 2)
void gemm_mma(const float* __restrict__ A, const float* __restrict__ Bw,
              const float* __restrict__ bias, float* __restrict__ C, int N)
{
    extern __shared__ char smem[];
    const uint32_t sbase = smem_to_u32(smem);
    const int tid  = threadIdx.x;
    const int lane = tid & 31;
    const int w    = tid >> 5;
    const int wm   = (w & 1) * 64;
    const int wn   = (w >> 1) * 64;
    const int gid  = lane >> 2;   // 0..7
    const int tig  = lane & 3;    // 0..3

    const size_t block_m = (size_t)blockIdx.y * 128;
    const int    block_n = blockIdx.x * 128;

    const int a_row = tid >> 3;        // +16*i
    const int a_c4  = tid & 7;
    const int b_k   = tid >> 5;        // +4*i
    const int b_c4  = tid & 31;

    float acc[4][8][4];
#pragma unroll
    for (int mi = 0; mi < 4; mi++)
#pragma unroll
        for (int ni = 0; ni < 8; ni++)
#pragma unroll
            for (int r = 0; r < 4; r++) acc[mi][ni][r] = 0.0f;

    constexpr int NS = K_TOTAL / 32;

    auto issue_tile = [&](int s, int buf) {
        if (s < NS) {
            const int k0 = s * 32;
            const uint32_t sA = sbase + buf * BUFBYTES;
            const uint32_t sB = sA + ABYTES;
#pragma unroll
            for (int i = 0; i < 8; i++) {
                int r = a_row + i * 16;
                cp_async16(sA + r * (LDA * 4) + a_c4 * 16,
                           &A[(block_m + r) * K_TOTAL + k0 + a_c4 * 4]);
            }
#pragma unroll
            for (int i = 0; i < 8; i++) {
                int k = b_k + i * 4;
                cp_async16(sB + k * (LDB * 4) + b_c4 * 16,
                           &Bw[(size_t)(k0 + k) * N + block_n + b_c4 * 4]);
            }
        }
        CP_COMMIT();
    };

    issue_tile(0, 0);
    issue_tile(1, 1);

    int buf = 0, buf2 = 2;   // buf: current compute buffer, buf2: (s+2)%3
    for (int s = 0; s < NS; s++) {
        CP_WAIT(1);
        __syncthreads();
        issue_tile(s + 2, buf2);

        const float* As = (const float*)(smem + buf * BUFBYTES);
        const float* Bs = (const float*)(smem + buf * BUFBYTES + ABYTES);

#pragma unroll
        for (int kk = 0; kk < 4; kk++) {
            const int kb = kk * 8;
            uint32_t bfr[8][2];
#pragma unroll
            for (int ni = 0; ni < 8; ni++) {
                int col = wn + ni * 8 + gid;
                bfr[ni][0] = __float_as_uint(Bs[(kb + tig)     * LDB + col]);
                bfr[ni][1] = __float_as_uint(Bs[(kb + tig + 4) * LDB + col]);
            }
#pragma unroll
            for (int mi = 0; mi < 4; mi++) {
                int r0 = wm + mi * 16 + gid;
                uint32_t a[4];
                a[0] = __float_as_uint(As[ r0      * LDA + kb + tig]);
                a[1] = __float_as_uint(As[(r0 + 8) * LDA + kb + tig]);
                a[2] = __float_as_uint(As[ r0      * LDA + kb + tig + 4]);
                a[3] = __float_as_uint(As[(r0 + 8) * LDA + kb + tig + 4]);
#pragma unroll
                for (int ni = 0; ni < 8; ni++)
                    mma_tf32(acc[mi][ni], a, bfr[ni]);
            }
        }
        // rotate buffers: buf <- buf+1, buf2 <- buf2+1 (mod 3)
        buf  = (buf  == 2) ? 0 : buf  + 1;
        buf2 = (buf2 == 2) ? 0 : buf2 + 1;
    }

    // store with bias (+ optional relu + tf32 round)
#pragma unroll
    for (int ni = 0; ni < 8; ni++) {
        int col = block_n + wn + ni * 8 + tig * 2;
        float bx = __ldg(&bias[col]);
        float by = __ldg(&bias[col + 1]);
#pragma unroll
        for (int mi = 0; mi < 4; mi++) {
            size_t r = block_m + wm + mi * 16 + gid;
            float v0 = acc[mi][ni][0] + bx;
            float v1 = acc[mi][ni][1] + by;
            float v2 = acc[mi][ni][2] + bx;
            float v3 = acc[mi][ni][3] + by;
            if (RELU_ROUND) {
                v0 = to_tf32(fmaxf(v0, 0.0f));
                v1 = to_tf32(fmaxf(v1, 0.0f));
                v2 = to_tf32(fmaxf(v2, 0.0f));
                v3 = to_tf32(fmaxf(v3, 0.0f));
            }
            float2 p0 = {v0, v1};
            float2 p1 = {v2, v3};
            *(float2*)&C[ r      * N + col] = p0;
            *(float2*)&C[(r + 8) * N + col] = p1;
        }
    }
}

// ---------------------------------------------------------------------------
// Epilogue: s = 5*tanh(st[:256]); t = st[256:]; y, log_det
// ---------------------------------------------------------------------------
__global__ __launch_bounds__(256)
void epilogue_kernel(const float* __restrict__ x,
                     float* __restrict__ out_y,
                     float* __restrict__ out_logdet)
{
    const int row = blockIdx.x;
    const int j   = threadIdx.x;   // 0..255

    const float* st = &g_st[(size_t)row * DIM];
    float s = tanhf(st[j]) * S_MAX;
    float t = st[256 + j];

    float2 x2 = *(const float2*)&x[(size_t)row * DIM + 2 * j];
    float2 y2;
    y2.x = x2.x;
    y2.y = fmaf(x2.y, expf(s), t);
    *(float2*)&out_y[(size_t)row * DIM + 2 * j] = y2;

    float v = s;
#pragma unroll
    for (int o = 16; o > 0; o >>= 1)
        v += __shfl_down_sync(0xFFFFFFFFu, v, o);

    __shared__ float red[8];
    int lane = j & 31, warp = j >> 5;
    if (lane == 0) red[warp] = v;
    __syncthreads();
    if (j == 0) {
        float total = 0.0f;
#pragma unroll
        for (int wq = 0; wq < 8; wq++) total += red[wq];
        out_logdet[row] = total;
    }
}

// ---------------------------------------------------------------------------
extern "C" void kernel_launch(void* const* d_in, const int* in_sizes, int n_in,
                              void* d_out, int out_size)
{
    const float* x   = (const float*)d_in[0];
    const float* ctx = (const float*)d_in[1];
    const float* W1  = (const float*)d_in[2];
    const float* b1  = (const float*)d_in[3];
    const float* W2  = (const float*)d_in[4];
    const float* b2  = (const float*)d_in[5];

    float* y      = (float*)d_out;
    float* logdet = (float*)d_out + (size_t)B_ROWS * DIM;

    float* A1;  cudaGetSymbolAddress((void**)&A1,  g_A1);
    float* hC;  cudaGetSymbolAddress((void**)&hC,  g_h);
    float* stC; cudaGetSymbolAddress((void**)&stC, g_st);
    float* W1r; cudaGetSymbolAddress((void**)&W1r, g_W1r);
    float* W2r; cudaGetSymbolAddress((void**)&W2r, g_W2r);

    cudaFuncSetAttribute(gemm_mma<KIN, true>,
                         cudaFuncAttributeMaxDynamicSharedMemorySize, GEMM_SMEM);
    cudaFuncSetAttribute(gemm_mma<HID, false>,
                         cudaFuncAttributeMaxDynamicSharedMemorySize, GEMM_SMEM);

    gather_kernel<<<(B_ROWS * 96) / 256, 256>>>(x, ctx);
    round_kernel<<<(KIN * HID / 4) / 256, 256>>>(W1, W1r);
    round_kernel<<<(HID * DIM / 4) / 256, 256>>>(W2, W2r);

    gemm_mma<KIN, true><<<dim3(HID / 128, B_ROWS / 128), 128, GEMM_SMEM>>>(
        A1, W1r, b1, hC, HID);

    gemm_mma<HID, false><<<dim3(DIM / 128, B_ROWS / 128), 128, GEMM_SMEM>>>(
        hC, W2r, b2, stC, DIM);

    epilogue_kernel<<<B_ROWS, 256>>>(x, y, logdet);
}

// round 5
// speedup vs baseline: 1.2138x; 1.2138x over previous
#include <cuda_runtime.h>
#include <cstdint>
#include <math.h>

#define B_ROWS 131072
#define DIM    512
#define CTX    128
#define HID    2048
#define KIN    384
#define S_MAX  5.0f

// ---------------------------------------------------------------------------
// Scratch device globals (no allocations allowed)
// ---------------------------------------------------------------------------
__device__ float g_A1 [(size_t)B_ROWS * KIN];   // gathered [x_even | ctx], tf32-rounded
__device__ float g_h  [(size_t)B_ROWS * HID];   // relu(A1 @ W1 + b1), tf32-rounded
__device__ float g_st [(size_t)B_ROWS * DIM];   // h @ W2 + b2
__device__ float g_W1r[(size_t)KIN * HID];      // W1 tf32-rounded
__device__ float g_W2r[(size_t)HID * DIM];      // W2 tf32-rounded

// ---------------------------------------------------------------------------
// helpers
// ---------------------------------------------------------------------------
__device__ __forceinline__ uint32_t smem_to_u32(const void* p) {
    uint32_t a;
    asm("{ .reg .u64 t; cvta.to.shared.u64 t, %1; cvt.u32.u64 %0, t; }" : "=r"(a) : "l"(p));
    return a;
}
__device__ __forceinline__ float to_tf32(float v) {
    uint32_t r;
    asm("cvt.rna.tf32.f32 %0, %1;" : "=r"(r) : "f"(v));
    return __uint_as_float(r);
}
__device__ __forceinline__ void cp_async16(uint32_t saddr, const void* gptr) {
    asm volatile("cp.async.ca.shared.global [%0], [%1], 16;" :: "r"(saddr), "l"(gptr));
}
#define CP_COMMIT() asm volatile("cp.async.commit_group;" ::: "memory")
#define CP_WAIT(n)  asm volatile("cp.async.wait_group %0;" :: "n"(n) : "memory")

__device__ __forceinline__ void mma_tf32(float* d, const uint32_t* a, const uint32_t* b) {
    asm volatile(
        "mma.sync.aligned.m16n8k8.row.col.f32.tf32.tf32.f32 "
        "{%0,%1,%2,%3}, {%4,%5,%6,%7}, {%8,%9}, {%0,%1,%2,%3};\n"
        : "+f"(d[0]), "+f"(d[1]), "+f"(d[2]), "+f"(d[3])
        : "r"(a[0]), "r"(a[1]), "r"(a[2]), "r"(a[3]), "r"(b[0]), "r"(b[1]));
}

// ---------------------------------------------------------------------------
// Prep kernels
// ---------------------------------------------------------------------------
__global__ __launch_bounds__(256)
void gather_kernel(const float* __restrict__ x, const float* __restrict__ ctx)
{
    int idx = blockIdx.x * 256 + threadIdx.x;          // over B_ROWS*96 float4s
    int b  = idx / 96;
    int k4 = idx % 96;
    float4 v;
    if (k4 < 64) {
        const float* xp = &x[(size_t)b * DIM + 8 * k4];
        v.x = xp[0]; v.y = xp[2]; v.z = xp[4]; v.w = xp[6];
    } else {
        v = *(const float4*)&ctx[(size_t)b * CTX + (k4 - 64) * 4];
    }
    v.x = to_tf32(v.x); v.y = to_tf32(v.y); v.z = to_tf32(v.z); v.w = to_tf32(v.w);
    *(float4*)&g_A1[(size_t)b * KIN + k4 * 4] = v;
}

__global__ __launch_bounds__(256)
void round_kernel(const float* __restrict__ src, float* __restrict__ dst)
{
    int idx = blockIdx.x * 256 + threadIdx.x;   // over n/4 float4s
    float4 v = *(const float4*)&src[idx * 4];
    v.x = to_tf32(v.x); v.y = to_tf32(v.y); v.z = to_tf32(v.z); v.w = to_tf32(v.w);
    *(float4*)&dst[idx * 4] = v;
}

// ---------------------------------------------------------------------------
// GEMM via mma.sync tf32. Block 128x128, 4 warps (64x64 each), BK=32,
// cp.async double buffer (R3 skeleton). All operands tf32-pre-rounded.
// ---------------------------------------------------------------------------
#define LDA 36     // floats; bank(4*gid + tig) bijective over lanes
#define LDB 136    // floats; bank(8*tig + gid) bijective over lanes
#define ABYTES (128 * LDA * 4)          // 18432
#define BBYTES (32 * LDB * 4)           // 17408
#define BUFBYTES (ABYTES + BBYTES)      // 35840
#define GEMM_SMEM (2 * BUFBYTES)        // 71680

template<int K_TOTAL, bool RELU_ROUND>
__global__ __launch_bounds__(128)
void gemm_mma(const float* __restrict__ A, const float* __restrict__ Bw,
              const float* __restrict__ bias, float* __restrict__ C, int N)
{
    extern __shared__ char smem[];
    const uint32_t sbase = smem_to_u32(smem);
    const int tid  = threadIdx.x;
    const int lane = tid & 31;
    const int w    = tid >> 5;
    const int wm   = (w & 1) * 64;
    const int wn   = (w >> 1) * 64;
    const int gid  = lane >> 2;   // 0..7
    const int tig  = lane & 3;    // 0..3

    const size_t block_m = (size_t)blockIdx.y * 128;
    const int    block_n = blockIdx.x * 128;

    const int a_row = tid >> 3;        // +16*i
    const int a_c4  = tid & 7;
    const int b_k   = tid >> 5;        // +4*i
    const int b_c4  = tid & 31;

    float acc[4][8][4];
#pragma unroll
    for (int mi = 0; mi < 4; mi++)
#pragma unroll
        for (int ni = 0; ni < 8; ni++)
#pragma unroll
            for (int r = 0; r < 4; r++) acc[mi][ni][r] = 0.0f;

    constexpr int NS = K_TOTAL / 32;

    auto issue_tile = [&](int s, int buf) {
        const int k0 = s * 32;
        const uint32_t sA = sbase + buf * BUFBYTES;
        const uint32_t sB = sA + ABYTES;
#pragma unroll
        for (int i = 0; i < 8; i++) {
            int r = a_row + i * 16;
            cp_async16(sA + r * (LDA * 4) + a_c4 * 16,
                       &A[(block_m + r) * K_TOTAL + k0 + a_c4 * 4]);
        }
#pragma unroll
        for (int i = 0; i < 8; i++) {
            int k = b_k + i * 4;
            cp_async16(sB + k * (LDB * 4) + b_c4 * 16,
                       &Bw[(size_t)(k0 + k) * N + block_n + b_c4 * 4]);
        }
        CP_COMMIT();
    };

    issue_tile(0, 0);

    // per-warp fragment base offsets (floats) hoisted out of the loop
    const int a_base = (wm + gid) * LDA + tig;   // + mi*16*LDA, +8*LDA, +4
    const int b_base = tig * LDB + wn + gid;     // + ni*8, +4*LDB

    for (int s = 0; s < NS; s++) {
        const int buf = s & 1;
        if (s + 1 < NS) {
            issue_tile(s + 1, buf ^ 1);
            CP_WAIT(1);
        } else {
            CP_WAIT(0);
        }
        __syncthreads();

        const float* As = (const float*)(smem + buf * BUFBYTES);
        const float* Bs = (const float*)(smem + buf * BUFBYTES + ABYTES);

#pragma unroll
        for (int kk = 0; kk < 4; kk++) {
            const int kb = kk * 8;
            uint32_t bfr[8][2];
#pragma unroll
            for (int ni = 0; ni < 8; ni++) {
                int o = kb * LDB + b_base + ni * 8;
                bfr[ni][0] = __float_as_uint(Bs[o]);
                bfr[ni][1] = __float_as_uint(Bs[o + 4 * LDB]);
            }
#pragma unroll
            for (int mi = 0; mi < 4; mi++) {
                int o = a_base + mi * 16 * LDA + kb;
                uint32_t a[4];
                a[0] = __float_as_uint(As[o]);
                a[1] = __float_as_uint(As[o + 8 * LDA]);
                a[2] = __float_as_uint(As[o + 4]);
                a[3] = __float_as_uint(As[o + 8 * LDA + 4]);
#pragma unroll
                for (int ni = 0; ni < 8; ni++)
                    mma_tf32(acc[mi][ni], a, bfr[ni]);
            }
        }
        __syncthreads();
    }

    // store with bias (+ optional relu + tf32 round)
#pragma unroll
    for (int ni = 0; ni < 8; ni++) {
        int col = block_n + wn + ni * 8 + tig * 2;
        float bx = __ldg(&bias[col]);
        float by = __ldg(&bias[col + 1]);
#pragma unroll
        for (int mi = 0; mi < 4; mi++) {
            size_t r = block_m + wm + mi * 16 + gid;
            float v0 = acc[mi][ni][0] + bx;
            float v1 = acc[mi][ni][1] + by;
            float v2 = acc[mi][ni][2] + bx;
            float v3 = acc[mi][ni][3] + by;
            if (RELU_ROUND) {
                v0 = to_tf32(fmaxf(v0, 0.0f));
                v1 = to_tf32(fmaxf(v1, 0.0f));
                v2 = to_tf32(fmaxf(v2, 0.0f));
                v3 = to_tf32(fmaxf(v3, 0.0f));
            }
            float2 p0 = {v0, v1};
            float2 p1 = {v2, v3};
            *(float2*)&C[ r      * N + col] = p0;
            *(float2*)&C[(r + 8) * N + col] = p1;
        }
    }
}

// ---------------------------------------------------------------------------
// Epilogue: s = 5*tanh(st[:256]); t = st[256:]; y, log_det
// ---------------------------------------------------------------------------
__global__ __launch_bounds__(256)
void epilogue_kernel(const float* __restrict__ x,
                     float* __restrict__ out_y,
                     float* __restrict__ out_logdet)
{
    const int row = blockIdx.x;
    const int j   = threadIdx.x;   // 0..255

    const float* st = &g_st[(size_t)row * DIM];
    float s = tanhf(st[j]) * S_MAX;
    float t = st[256 + j];

    float2 x2 = *(const float2*)&x[(size_t)row * DIM + 2 * j];
    float2 y2;
    y2.x = x2.x;
    y2.y = fmaf(x2.y, expf(s), t);
    *(float2*)&out_y[(size_t)row * DIM + 2 * j] = y2;

    float v = s;
#pragma unroll
    for (int o = 16; o > 0; o >>= 1)
        v += __shfl_down_sync(0xFFFFFFFFu, v, o);

    __shared__ float red[8];
    int lane = j & 31, warp = j >> 5;
    if (lane == 0) red[warp] = v;
    __syncthreads();
    if (j == 0) {
        float total = 0.0f;
#pragma unroll
        for (int wq = 0; wq < 8; wq++) total += red[wq];
        out_logdet[row] = total;
    }
}

// ---------------------------------------------------------------------------
extern "C" void kernel_launch(void* const* d_in, const int* in_sizes, int n_in,
                              void* d_out, int out_size)
{
    const float* x   = (const float*)d_in[0];
    const float* ctx = (const float*)d_in[1];
    const float* W1  = (const float*)d_in[2];
    const float* b1  = (const float*)d_in[3];
    const float* W2  = (const float*)d_in[4];
    const float* b2  = (const float*)d_in[5];

    float* y      = (float*)d_out;
    float* logdet = (float*)d_out + (size_t)B_ROWS * DIM;

    float* A1;  cudaGetSymbolAddress((void**)&A1,  g_A1);
    float* hC;  cudaGetSymbolAddress((void**)&hC,  g_h);
    float* stC; cudaGetSymbolAddress((void**)&stC, g_st);
    float* W1r; cudaGetSymbolAddress((void**)&W1r, g_W1r);
    float* W2r; cudaGetSymbolAddress((void**)&W2r, g_W2r);

    cudaFuncSetAttribute(gemm_mma<KIN, true>,
                         cudaFuncAttributeMaxDynamicSharedMemorySize, GEMM_SMEM);
    cudaFuncSetAttribute(gemm_mma<HID, false>,
                         cudaFuncAttributeMaxDynamicSharedMemorySize, GEMM_SMEM);

    gather_kernel<<<(B_ROWS * 96) / 256, 256>>>(x, ctx);
    round_kernel<<<(KIN * HID / 4) / 256, 256>>>(W1, W1r);
    round_kernel<<<(HID * DIM / 4) / 256, 256>>>(W2, W2r);

    gemm_mma<KIN, true><<<dim3(HID / 128, B_ROWS / 128), 128, GEMM_SMEM>>>(
        A1, W1r, b1, hC, HID);

    gemm_mma<HID, false><<<dim3(DIM / 128, B_ROWS / 128), 128, GEMM_SMEM>>>(
        hC, W2r, b2, stC, DIM);

    epilogue_kernel<<<B_ROWS, 256>>>(x, y, logdet);
}